// round 1
// baseline (speedup 1.0000x reference)
#include <cuda_runtime.h>
#include <math.h>

#define SEQ 2048
#define DIM 1280
#define NH  16
#define HD  80

// Scratch (device globals: no allocation allowed in kernel_launch)
__device__ float g_Q[SEQ * DIM];
__device__ float g_K[SEQ * DIM];
__device__ float g_V[SEQ * DIM];
__device__ float g_A[SEQ * DIM];

// ---------------------------------------------------------------------------
// SGEMM (NT): C[M,N] = A[M,K] * B[N,K]^T + bias[N]
// BM=BN=128, BK=16, 256 threads, 8x8 register microtiles.
// ---------------------------------------------------------------------------
#define BM 128
#define BN 128
#define BK 16
#define APAD 132   // row length of smem tiles (keeps 16B alignment, reduces conflicts)

__global__ __launch_bounds__(256, 2)
void sgemm_nt_bias(const float* __restrict__ A, const float* __restrict__ B,
                   const float* __restrict__ bias, float* __restrict__ C,
                   int M, int N, int K)
{
    __shared__ float As[BK][APAD];
    __shared__ float Bs[BK][APAD];

    const int tid = threadIdx.x;
    const int m0 = blockIdx.y * BM;
    const int n0 = blockIdx.x * BN;

    const int warp = tid >> 5, lane = tid & 31;
    const int wm = warp >> 1, wn = warp & 1;   // 4x2 warp grid
    const int lm = lane >> 3, ln = lane & 7;   // 4x8 lanes in warp
    const int row0 = wm * 32 + lm * 8;         // 0..120
    const int col0 = wn * 64 + ln * 8;         // 0..120

    float acc[8][8];
#pragma unroll
    for (int i = 0; i < 8; i++)
#pragma unroll
        for (int j = 0; j < 8; j++) acc[i][j] = 0.f;

    for (int kt = 0; kt < K; kt += BK) {
        // Load 128x16 tiles of A and B (transposed into [k][row] layout)
#pragma unroll
        for (int it = 0; it < 2; it++) {
            int i = tid + it * 256;          // 0..511
            int r  = i >> 2;                 // 0..127
            int kc = (i & 3) << 2;           // 0,4,8,12
            float4 a = *(const float4*)(A + (size_t)(m0 + r) * K + kt + kc);
            As[kc + 0][r] = a.x; As[kc + 1][r] = a.y;
            As[kc + 2][r] = a.z; As[kc + 3][r] = a.w;
            float4 b = *(const float4*)(B + (size_t)(n0 + r) * K + kt + kc);
            Bs[kc + 0][r] = b.x; Bs[kc + 1][r] = b.y;
            Bs[kc + 2][r] = b.z; Bs[kc + 3][r] = b.w;
        }
        __syncthreads();

#pragma unroll
        for (int k = 0; k < BK; k++) {
            float4 a0 = *(const float4*)&As[k][row0];
            float4 a1 = *(const float4*)&As[k][row0 + 4];
            float4 b0 = *(const float4*)&Bs[k][col0];
            float4 b1 = *(const float4*)&Bs[k][col0 + 4];
            float ar[8] = {a0.x, a0.y, a0.z, a0.w, a1.x, a1.y, a1.z, a1.w};
            float br[8] = {b0.x, b0.y, b0.z, b0.w, b1.x, b1.y, b1.z, b1.w};
#pragma unroll
            for (int i = 0; i < 8; i++)
#pragma unroll
                for (int j = 0; j < 8; j++)
                    acc[i][j] += ar[i] * br[j];
        }
        __syncthreads();
    }

    // Epilogue: + bias, vectorized stores
#pragma unroll
    for (int i = 0; i < 8; i++) {
        int r = m0 + row0 + i;
#pragma unroll
        for (int jj = 0; jj < 2; jj++) {
            int c = n0 + col0 + jj * 4;
            float4 bb = *(const float4*)(bias + c);
            float4 v;
            v.x = acc[i][jj * 4 + 0] + bb.x;
            v.y = acc[i][jj * 4 + 1] + bb.y;
            v.z = acc[i][jj * 4 + 2] + bb.z;
            v.w = acc[i][jj * 4 + 3] + bb.w;
            *(float4*)(C + (size_t)r * N + c) = v;
        }
    }
}

// ---------------------------------------------------------------------------
// RoPE (in-place on g_Q and g_K).
// out[j]    = x[j]*cos[j]    - x[j+40]*sin[j]        (j < 40)
// out[j+40] = x[j+40]*cos[j+40] + x[j]*sin[j+40]
// ---------------------------------------------------------------------------
__global__ void rope_kernel(const float* __restrict__ cs, const float* __restrict__ sn)
{
    int idx = blockIdx.x * blockDim.x + threadIdx.x;
    const int total = SEQ * NH * (HD / 2);
    if (idx >= total) return;
    int j = idx % (HD / 2);
    int h = (idx / (HD / 2)) % NH;
    int s = idx / ((HD / 2) * NH);
    int base = s * DIM + h * HD;
    float c0 = cs[s * HD + j],      s0 = sn[s * HD + j];
    float c1 = cs[s * HD + j + 40], s1 = sn[s * HD + j + 40];
    {
        float x0 = g_Q[base + j], x1 = g_Q[base + j + 40];
        g_Q[base + j]      = x0 * c0 - x1 * s0;
        g_Q[base + j + 40] = x1 * c1 + x0 * s1;
    }
    {
        float x0 = g_K[base + j], x1 = g_K[base + j + 40];
        g_K[base + j]      = x0 * c0 - x1 * s0;
        g_K[base + j + 40] = x1 * c1 + x0 * s1;
    }
}

// ---------------------------------------------------------------------------
// Segmented flash attention.
// Block = (32-query tile, head). 256 threads as 16x16.
// Score tile 32x64 (2x4 per thread); output 32x80 (2x5 per thread).
// Keys restricted to the query tile's segment (block-diagonal mask).
// ---------------------------------------------------------------------------
__global__ __launch_bounds__(256)
void attn_kernel(const int* __restrict__ cu, float* __restrict__ out)
{
    __shared__ float Qs[32][81];
    __shared__ float KV[64][81];
    __shared__ float Ps[32][68];

    const int tid = threadIdx.x;
    const int ty = tid >> 4, tx = tid & 15;
    const int qb = blockIdx.x * 32;
    const int h  = blockIdx.y;

    int ks = 0, ke = SEQ;
#pragma unroll
    for (int i = 0; i < 4; i++)
        if (qb >= cu[i] && qb < cu[i + 1]) { ks = cu[i]; ke = cu[i + 1]; }

    const float scale = rsqrtf((float)HD);

    // Load + pre-scale Q tile
    for (int i = tid; i < 32 * HD; i += 256) {
        int r = i / HD, d = i % HD;
        Qs[r][d] = g_Q[(size_t)(qb + r) * DIM + h * HD + d] * scale;
    }

    const int r0 = ty * 2;
    const int c0 = tx * 4;
    const int v0 = tx * 5;

    float m[2] = {-1e30f, -1e30f};
    float l[2] = {0.f, 0.f};
    float o[2][5];
#pragma unroll
    for (int i = 0; i < 2; i++)
#pragma unroll
        for (int j = 0; j < 5; j++) o[i][j] = 0.f;

    for (int kt = ks; kt < ke; kt += 64) {
        int kn = min(64, ke - kt);
        __syncthreads();
        // K tile
        for (int i = tid; i < 64 * HD; i += 256) {
            int r = i / HD, d = i % HD;
            KV[r][d] = (r < kn) ? g_K[(size_t)(kt + r) * DIM + h * HD + d] : 0.f;
        }
        __syncthreads();

        // S = Q K^T (2x4 per thread)
        float sc[2][4] = {{0.f, 0.f, 0.f, 0.f}, {0.f, 0.f, 0.f, 0.f}};
#pragma unroll 4
        for (int d = 0; d < HD; d++) {
            float q0 = Qs[r0][d], q1 = Qs[r0 + 1][d];
            float k0 = KV[c0][d], k1 = KV[c0 + 1][d];
            float k2 = KV[c0 + 2][d], k3 = KV[c0 + 3][d];
            sc[0][0] += q0 * k0; sc[0][1] += q0 * k1;
            sc[0][2] += q0 * k2; sc[0][3] += q0 * k3;
            sc[1][0] += q1 * k0; sc[1][1] += q1 * k1;
            sc[1][2] += q1 * k2; sc[1][3] += q1 * k3;
        }
#pragma unroll
        for (int j = 0; j < 4; j++)
            if (c0 + j >= kn) { sc[0][j] = -1e30f; sc[1][j] = -1e30f; }

        // Online softmax update (row state replicated over the 16 tx lanes)
        float fac[2], rsum[2];
#pragma unroll
        for (int i = 0; i < 2; i++) {
            float mloc = fmaxf(fmaxf(sc[i][0], sc[i][1]), fmaxf(sc[i][2], sc[i][3]));
#pragma unroll
            for (int off = 1; off < 16; off <<= 1)
                mloc = fmaxf(mloc, __shfl_xor_sync(0xffffffffu, mloc, off));
            float mn = fmaxf(m[i], mloc);
            fac[i] = __expf(m[i] - mn);
            m[i] = mn;
            float rs = 0.f;
#pragma unroll
            for (int j = 0; j < 4; j++) {
                float p = __expf(sc[i][j] - mn);
                sc[i][j] = p;
                rs += p;
            }
#pragma unroll
            for (int off = 1; off < 16; off <<= 1)
                rs += __shfl_xor_sync(0xffffffffu, rs, off);
            rsum[i] = rs;
            l[i] = l[i] * fac[i] + rsum[i];
#pragma unroll
            for (int j = 0; j < 5; j++) o[i][j] *= fac[i];
#pragma unroll
            for (int j = 0; j < 4; j++) Ps[r0 + i][c0 + j] = sc[i][j];
        }
        __syncthreads();

        // V tile (reuse KV buffer)
        for (int i = tid; i < 64 * HD; i += 256) {
            int r = i / HD, d = i % HD;
            KV[r][d] = (r < kn) ? g_V[(size_t)(kt + r) * DIM + h * HD + d] : 0.f;
        }
        __syncthreads();

        // O += P V (2x5 per thread)
#pragma unroll 4
        for (int c = 0; c < 64; c++) {
            float p0 = Ps[r0][c], p1 = Ps[r0 + 1][c];
#pragma unroll
            for (int j = 0; j < 5; j++) {
                float v = KV[c][v0 + j];
                o[0][j] += p0 * v;
                o[1][j] += p1 * v;
            }
        }
    }

#pragma unroll
    for (int i = 0; i < 2; i++) {
        float inv = 1.f / l[i];
#pragma unroll
        for (int j = 0; j < 5; j++)
            out[(size_t)(qb + r0 + i) * DIM + h * HD + v0 + j] = o[i][j] * inv;
    }
}

// ---------------------------------------------------------------------------
extern "C" void kernel_launch(void* const* d_in, const int* in_sizes, int n_in,
                              void* d_out, int out_size)
{
    const float* X  = (const float*)d_in[0];
    const float* Wq = (const float*)d_in[1];
    const float* bq = (const float*)d_in[2];
    const float* Wk = (const float*)d_in[3];
    const float* bk = (const float*)d_in[4];
    const float* Wv = (const float*)d_in[5];
    const float* bv = (const float*)d_in[6];
    const float* Wo = (const float*)d_in[7];
    const float* bo = (const float*)d_in[8];
    const float* cs = (const float*)d_in[9];
    const float* sn = (const float*)d_in[10];
    const int*   cu = (const int*)d_in[11];
    float* out = (float*)d_out;

    void *pQ, *pK, *pV, *pA;
    cudaGetSymbolAddress(&pQ, g_Q);
    cudaGetSymbolAddress(&pK, g_K);
    cudaGetSymbolAddress(&pV, g_V);
    cudaGetSymbolAddress(&pA, g_A);

    dim3 gg(DIM / BN, SEQ / BM);  // (10, 16)
    dim3 gb(256);

    // Q/K/V projections
    sgemm_nt_bias<<<gg, gb>>>(X, Wq, bq, (float*)pQ, SEQ, DIM, DIM);
    sgemm_nt_bias<<<gg, gb>>>(X, Wk, bk, (float*)pK, SEQ, DIM, DIM);
    sgemm_nt_bias<<<gg, gb>>>(X, Wv, bv, (float*)pV, SEQ, DIM, DIM);

    // RoPE in place on Q, K
    int rope_total = SEQ * NH * (HD / 2);
    rope_kernel<<<(rope_total + 255) / 256, 256>>>(cs, sn);

    // Segmented attention -> g_A [S, D]
    dim3 ga(SEQ / 32, NH);
    attn_kernel<<<ga, gb>>>(cu, (float*)pA);

    // Output projection -> d_out
    sgemm_nt_bias<<<gg, gb>>>((const float*)pA, Wo, bo, out, SEQ, DIM, DIM);
}

// round 2
// speedup vs baseline: 2.0594x; 2.0594x over previous
#include <cuda_runtime.h>
#include <math.h>
#include <stdint.h>

#define SEQ 2048
#define DIM 1280
#define NH  16
#define HD  80

// Scratch (device globals: no allocation allowed in kernel_launch)
__device__ float g_Q[SEQ * DIM];
__device__ float g_K[SEQ * DIM];
__device__ float g_V[SEQ * DIM];
__device__ float g_A[SEQ * DIM];

// ---------------------------------------------------------------------------
// TF32 tensor-core GEMM (NT): C[M,N] = A[M,K] * B[N,K]^T + bias[N]
// BM=BN=128, BK=32, 256 threads (8 warps as 2x4), warp tile 64x32,
// mma.sync.m16n8k8.tf32 with fp32 accumulate. Inputs rounded with cvt.rna.
// Smem row stride 36 words -> fragment LDS addresses (4g+tg) mod 32: conflict-free.
// ---------------------------------------------------------------------------
#define BM 128
#define BN 128
#define BK 32
#define SST 36   // smem row stride (words)

__device__ __forceinline__ float f2tf32(float x) {
    uint32_t u;
    asm("cvt.rna.tf32.f32 %0, %1;" : "=r"(u) : "f"(x));
    return __uint_as_float(u);
}

__device__ __forceinline__ void mma_tf32(float* c, const uint32_t* a, const uint32_t* b) {
    asm("mma.sync.aligned.m16n8k8.row.col.f32.tf32.tf32.f32 "
        "{%0,%1,%2,%3}, {%4,%5,%6,%7}, {%8,%9}, {%0,%1,%2,%3};"
        : "+f"(c[0]), "+f"(c[1]), "+f"(c[2]), "+f"(c[3])
        : "r"(a[0]), "r"(a[1]), "r"(a[2]), "r"(a[3]), "r"(b[0]), "r"(b[1]));
}

__global__ __launch_bounds__(256, 2)
void gemm_tf32_nt_bias(const float* __restrict__ A, const float* __restrict__ B,
                       const float* __restrict__ bias, float* __restrict__ C,
                       int M, int N, int K)
{
    __shared__ float As[BM][SST];
    __shared__ float Bs[BN][SST];

    const int tid = threadIdx.x;
    const int m0 = blockIdx.y * BM;
    const int n0 = blockIdx.x * BN;

    const int warp = tid >> 5, lane = tid & 31;
    const int wm = warp >> 2;            // 0..1  -> 64-row warp tile
    const int wn = warp & 3;             // 0..3  -> 32-col warp tile
    const int g  = lane >> 2;            // 0..7
    const int tg = lane & 3;             // 0..3

    float acc[4][4][4];
#pragma unroll
    for (int mt = 0; mt < 4; mt++)
#pragma unroll
        for (int nt = 0; nt < 4; nt++)
#pragma unroll
            for (int r = 0; r < 4; r++) acc[mt][nt][r] = 0.f;

    for (int kt = 0; kt < K; kt += BK) {
        // Load 128x32 tiles of A and B; convert to tf32 (rna) at smem-store time.
#pragma unroll
        for (int t = 0; t < 4; t++) {
            int idx = tid + t * 256;      // 0..1023
            int r   = idx >> 3;           // 0..127
            int kc  = (idx & 7) << 2;     // 0..28
            float4 a = *(const float4*)(A + (size_t)(m0 + r) * K + kt + kc);
            float4 av = make_float4(f2tf32(a.x), f2tf32(a.y), f2tf32(a.z), f2tf32(a.w));
            *(float4*)&As[r][kc] = av;
            float4 b = *(const float4*)(B + (size_t)(n0 + r) * K + kt + kc);
            float4 bv = make_float4(f2tf32(b.x), f2tf32(b.y), f2tf32(b.z), f2tf32(b.w));
            *(float4*)&Bs[r][kc] = bv;
        }
        __syncthreads();

#pragma unroll
        for (int ks = 0; ks < 4; ks++) {
            const int k0 = ks * 8;
            uint32_t af[4][4], bf[4][2];
#pragma unroll
            for (int mt = 0; mt < 4; mt++) {
                int r = wm * 64 + mt * 16 + g;
                af[mt][0] = __float_as_uint(As[r][k0 + tg]);
                af[mt][1] = __float_as_uint(As[r + 8][k0 + tg]);
                af[mt][2] = __float_as_uint(As[r][k0 + tg + 4]);
                af[mt][3] = __float_as_uint(As[r + 8][k0 + tg + 4]);
            }
#pragma unroll
            for (int nt = 0; nt < 4; nt++) {
                int c = wn * 32 + nt * 8 + g;
                bf[nt][0] = __float_as_uint(Bs[c][k0 + tg]);
                bf[nt][1] = __float_as_uint(Bs[c][k0 + tg + 4]);
            }
#pragma unroll
            for (int mt = 0; mt < 4; mt++)
#pragma unroll
                for (int nt = 0; nt < 4; nt++)
                    mma_tf32(acc[mt][nt], af[mt], bf[nt]);
        }
        __syncthreads();
    }

    // Epilogue: + bias, float2 stores per C fragment row
#pragma unroll
    for (int mt = 0; mt < 4; mt++) {
#pragma unroll
        for (int nt = 0; nt < 4; nt++) {
            int r = m0 + wm * 64 + mt * 16 + g;
            int c = n0 + wn * 32 + nt * 8 + 2 * tg;
            float2 bb = *(const float2*)(bias + c);
            float2 v0 = make_float2(acc[mt][nt][0] + bb.x, acc[mt][nt][1] + bb.y);
            float2 v1 = make_float2(acc[mt][nt][2] + bb.x, acc[mt][nt][3] + bb.y);
            *(float2*)(C + (size_t)r * N + c) = v0;
            *(float2*)(C + (size_t)(r + 8) * N + c) = v1;
        }
    }
}

// ---------------------------------------------------------------------------
// RoPE (in-place on g_Q and g_K).
// ---------------------------------------------------------------------------
__global__ void rope_kernel(const float* __restrict__ cs, const float* __restrict__ sn)
{
    int idx = blockIdx.x * blockDim.x + threadIdx.x;
    const int total = SEQ * NH * (HD / 2);
    if (idx >= total) return;
    int j = idx % (HD / 2);
    int h = (idx / (HD / 2)) % NH;
    int s = idx / ((HD / 2) * NH);
    int base = s * DIM + h * HD;
    float c0 = cs[s * HD + j],      s0 = sn[s * HD + j];
    float c1 = cs[s * HD + j + 40], s1 = sn[s * HD + j + 40];
    {
        float x0 = g_Q[base + j], x1 = g_Q[base + j + 40];
        g_Q[base + j]      = x0 * c0 - x1 * s0;
        g_Q[base + j + 40] = x1 * c1 + x0 * s1;
    }
    {
        float x0 = g_K[base + j], x1 = g_K[base + j + 40];
        g_K[base + j]      = x0 * c0 - x1 * s0;
        g_K[base + j + 40] = x1 * c1 + x0 * s1;
    }
}

// ---------------------------------------------------------------------------
// Segmented flash attention (unchanged from R1 — known correct).
// ---------------------------------------------------------------------------
__global__ __launch_bounds__(256)
void attn_kernel(const int* __restrict__ cu, float* __restrict__ out)
{
    __shared__ float Qs[32][81];
    __shared__ float KV[64][81];
    __shared__ float Ps[32][68];

    const int tid = threadIdx.x;
    const int ty = tid >> 4, tx = tid & 15;
    const int qb = blockIdx.x * 32;
    const int h  = blockIdx.y;

    int ks = 0, ke = SEQ;
#pragma unroll
    for (int i = 0; i < 4; i++)
        if (qb >= cu[i] && qb < cu[i + 1]) { ks = cu[i]; ke = cu[i + 1]; }

    const float scale = rsqrtf((float)HD);

    for (int i = tid; i < 32 * HD; i += 256) {
        int r = i / HD, d = i % HD;
        Qs[r][d] = g_Q[(size_t)(qb + r) * DIM + h * HD + d] * scale;
    }

    const int r0 = ty * 2;
    const int c0 = tx * 4;
    const int v0 = tx * 5;

    float m[2] = {-1e30f, -1e30f};
    float l[2] = {0.f, 0.f};
    float o[2][5];
#pragma unroll
    for (int i = 0; i < 2; i++)
#pragma unroll
        for (int j = 0; j < 5; j++) o[i][j] = 0.f;

    for (int kt = ks; kt < ke; kt += 64) {
        int kn = min(64, ke - kt);
        __syncthreads();
        for (int i = tid; i < 64 * HD; i += 256) {
            int r = i / HD, d = i % HD;
            KV[r][d] = (r < kn) ? g_K[(size_t)(kt + r) * DIM + h * HD + d] : 0.f;
        }
        __syncthreads();

        float sc[2][4] = {{0.f, 0.f, 0.f, 0.f}, {0.f, 0.f, 0.f, 0.f}};
#pragma unroll 4
        for (int d = 0; d < HD; d++) {
            float q0 = Qs[r0][d], q1 = Qs[r0 + 1][d];
            float k0 = KV[c0][d], k1 = KV[c0 + 1][d];
            float k2 = KV[c0 + 2][d], k3 = KV[c0 + 3][d];
            sc[0][0] += q0 * k0; sc[0][1] += q0 * k1;
            sc[0][2] += q0 * k2; sc[0][3] += q0 * k3;
            sc[1][0] += q1 * k0; sc[1][1] += q1 * k1;
            sc[1][2] += q1 * k2; sc[1][3] += q1 * k3;
        }
#pragma unroll
        for (int j = 0; j < 4; j++)
            if (c0 + j >= kn) { sc[0][j] = -1e30f; sc[1][j] = -1e30f; }

        float fac[2], rsum[2];
#pragma unroll
        for (int i = 0; i < 2; i++) {
            float mloc = fmaxf(fmaxf(sc[i][0], sc[i][1]), fmaxf(sc[i][2], sc[i][3]));
#pragma unroll
            for (int off = 1; off < 16; off <<= 1)
                mloc = fmaxf(mloc, __shfl_xor_sync(0xffffffffu, mloc, off));
            float mn = fmaxf(m[i], mloc);
            fac[i] = __expf(m[i] - mn);
            m[i] = mn;
            float rs = 0.f;
#pragma unroll
            for (int j = 0; j < 4; j++) {
                float p = __expf(sc[i][j] - mn);
                sc[i][j] = p;
                rs += p;
            }
#pragma unroll
            for (int off = 1; off < 16; off <<= 1)
                rs += __shfl_xor_sync(0xffffffffu, rs, off);
            rsum[i] = rs;
            l[i] = l[i] * fac[i] + rsum[i];
#pragma unroll
            for (int j = 0; j < 5; j++) o[i][j] *= fac[i];
#pragma unroll
            for (int j = 0; j < 4; j++) Ps[r0 + i][c0 + j] = sc[i][j];
        }
        __syncthreads();

        for (int i = tid; i < 64 * HD; i += 256) {
            int r = i / HD, d = i % HD;
            KV[r][d] = (r < kn) ? g_V[(size_t)(kt + r) * DIM + h * HD + d] : 0.f;
        }
        __syncthreads();

#pragma unroll 4
        for (int c = 0; c < 64; c++) {
            float p0 = Ps[r0][c], p1 = Ps[r0 + 1][c];
#pragma unroll
            for (int j = 0; j < 5; j++) {
                float v = KV[c][v0 + j];
                o[0][j] += p0 * v;
                o[1][j] += p1 * v;
            }
        }
    }

#pragma unroll
    for (int i = 0; i < 2; i++) {
        float inv = 1.f / l[i];
#pragma unroll
        for (int j = 0; j < 5; j++)
            out[(size_t)(qb + r0 + i) * DIM + h * HD + v0 + j] = o[i][j] * inv;
    }
}

// ---------------------------------------------------------------------------
extern "C" void kernel_launch(void* const* d_in, const int* in_sizes, int n_in,
                              void* d_out, int out_size)
{
    const float* X  = (const float*)d_in[0];
    const float* Wq = (const float*)d_in[1];
    const float* bq = (const float*)d_in[2];
    const float* Wk = (const float*)d_in[3];
    const float* bk = (const float*)d_in[4];
    const float* Wv = (const float*)d_in[5];
    const float* bv = (const float*)d_in[6];
    const float* Wo = (const float*)d_in[7];
    const float* bo = (const float*)d_in[8];
    const float* cs = (const float*)d_in[9];
    const float* sn = (const float*)d_in[10];
    const int*   cu = (const int*)d_in[11];
    float* out = (float*)d_out;

    void *pQ, *pK, *pV, *pA;
    cudaGetSymbolAddress(&pQ, g_Q);
    cudaGetSymbolAddress(&pK, g_K);
    cudaGetSymbolAddress(&pV, g_V);
    cudaGetSymbolAddress(&pA, g_A);

    dim3 gg(DIM / BN, SEQ / BM);  // (10, 16)
    dim3 gb(256);

    gemm_tf32_nt_bias<<<gg, gb>>>(X, Wq, bq, (float*)pQ, SEQ, DIM, DIM);
    gemm_tf32_nt_bias<<<gg, gb>>>(X, Wk, bk, (float*)pK, SEQ, DIM, DIM);
    gemm_tf32_nt_bias<<<gg, gb>>>(X, Wv, bv, (float*)pV, SEQ, DIM, DIM);

    int rope_total = SEQ * NH * (HD / 2);
    rope_kernel<<<(rope_total + 255) / 256, 256>>>(cs, sn);

    dim3 ga(SEQ / 32, NH);
    attn_kernel<<<ga, gb>>>(cu, (float*)pA);

    gemm_tf32_nt_bias<<<gg, gb>>>((const float*)pA, Wo, bo, out, SEQ, DIM, DIM);
}

// round 3
// speedup vs baseline: 2.1883x; 1.0626x over previous
#include <cuda_runtime.h>
#include <math.h>
#include <stdint.h>

#define SEQ 2048
#define DIM 1280
#define NH  16
#define HD  80

// Scratch (device globals)
__device__ float g_Q[SEQ * DIM];
__device__ float g_K[SEQ * DIM];
__device__ float g_Vt[SEQ * DIM];   // V transposed: [DIM][SEQ]
__device__ float g_A[SEQ * DIM];

__device__ __forceinline__ float f2tf32(float x) {
    uint32_t u;
    asm("cvt.rna.tf32.f32 %0, %1;" : "=r"(u) : "f"(x));
    return __uint_as_float(u);
}

__device__ __forceinline__ void mma_tf32(float* c, const uint32_t* a, const uint32_t* b) {
    asm("mma.sync.aligned.m16n8k8.row.col.f32.tf32.tf32.f32 "
        "{%0,%1,%2,%3}, {%4,%5,%6,%7}, {%8,%9}, {%0,%1,%2,%3};"
        : "+f"(c[0]), "+f"(c[1]), "+f"(c[2]), "+f"(c[3])
        : "r"(a[0]), "r"(a[1]), "r"(a[2]), "r"(a[3]), "r"(b[0]), "r"(b[1]));
}

// ---------------------------------------------------------------------------
// TF32 GEMM (NT), 2-stage cp.async pipeline.
// C[M,N] = A[M,K] B[N,K]^T + bias.  TRANS: store C transposed [N][M].
// BM=BN=128, BK=32, 256 thr (2x4 warps), warp tile 64x32.
// Raw fp32 staged via cp.async; cvt.rna.tf32 applied at fragment load.
// ---------------------------------------------------------------------------
#define BM 128
#define BN 128
#define BK 32
#define SST 36
#define GEMM_SMEM (2 * 2 * BM * SST * 4)   // 73728 B

__device__ __forceinline__ void cp16(uint32_t dst, const void* src) {
    asm volatile("cp.async.cg.shared.global [%0], [%1], 16;\n" :: "r"(dst), "l"(src));
}

template<bool TRANS>
__global__ __launch_bounds__(256, 2)
void gemm_tf32_pipe(const float* __restrict__ A, const float* __restrict__ B,
                    const float* __restrict__ bias, float* __restrict__ C,
                    int M, int N, int K)
{
    extern __shared__ float sm[];
    float* As = sm;                    // [2][BM*SST]
    float* Bs = sm + 2 * BM * SST;

    const int tid = threadIdx.x;
    const int m0 = blockIdx.y * BM;
    const int n0 = blockIdx.x * BN;

    const int warp = tid >> 5, lane = tid & 31;
    const int wm = warp >> 2, wn = warp & 3;
    const int g = lane >> 2, tg = lane & 3;

    const uint32_t sA = (uint32_t)__cvta_generic_to_shared(As);
    const uint32_t sB = (uint32_t)__cvta_generic_to_shared(Bs);

    float acc[4][4][4];
#pragma unroll
    for (int mt = 0; mt < 4; mt++)
#pragma unroll
        for (int nt = 0; nt < 4; nt++)
#pragma unroll
            for (int r = 0; r < 4; r++) acc[mt][nt][r] = 0.f;

    const int T = K / BK;   // 40

    auto issue = [&](int stage, int kt) {
#pragma unroll
        for (int t = 0; t < 4; t++) {
            int idx = tid + t * 256;
            int r = idx >> 3;
            int kc = (idx & 7) << 2;
            uint32_t off = (uint32_t)(stage * BM * SST + r * SST + kc) * 4u;
            cp16(sA + off, A + (size_t)(m0 + r) * K + kt + kc);
            cp16(sB + off, B + (size_t)(n0 + r) * K + kt + kc);
        }
        asm volatile("cp.async.commit_group;\n");
    };

    issue(0, 0);

    for (int ti = 0; ti < T; ti++) {
        if (ti + 1 < T) {
            issue((ti + 1) & 1, (ti + 1) * BK);
            asm volatile("cp.async.wait_group 1;\n");
        } else {
            asm volatile("cp.async.wait_group 0;\n");
        }
        __syncthreads();

        const float* Asr = As + (ti & 1) * BM * SST;
        const float* Bsr = Bs + (ti & 1) * BM * SST;

#pragma unroll
        for (int ks = 0; ks < 4; ks++) {
            const int k0 = ks * 8;
            uint32_t af[4][4], bf[4][2];
#pragma unroll
            for (int mt = 0; mt < 4; mt++) {
                int r = wm * 64 + mt * 16 + g;
                af[mt][0] = __float_as_uint(f2tf32(Asr[r * SST + k0 + tg]));
                af[mt][1] = __float_as_uint(f2tf32(Asr[(r + 8) * SST + k0 + tg]));
                af[mt][2] = __float_as_uint(f2tf32(Asr[r * SST + k0 + tg + 4]));
                af[mt][3] = __float_as_uint(f2tf32(Asr[(r + 8) * SST + k0 + tg + 4]));
            }
#pragma unroll
            for (int nt = 0; nt < 4; nt++) {
                int c = wn * 32 + nt * 8 + g;
                bf[nt][0] = __float_as_uint(f2tf32(Bsr[c * SST + k0 + tg]));
                bf[nt][1] = __float_as_uint(f2tf32(Bsr[c * SST + k0 + tg + 4]));
            }
#pragma unroll
            for (int mt = 0; mt < 4; mt++)
#pragma unroll
                for (int nt = 0; nt < 4; nt++)
                    mma_tf32(acc[mt][nt], af[mt], bf[nt]);
        }
        __syncthreads();
    }

#pragma unroll
    for (int mt = 0; mt < 4; mt++) {
#pragma unroll
        for (int nt = 0; nt < 4; nt++) {
            int r = m0 + wm * 64 + mt * 16 + g;
            int c = n0 + wn * 32 + nt * 8 + 2 * tg;
            float2 bb = *(const float2*)(bias + c);
            if (!TRANS) {
                float2 v0 = make_float2(acc[mt][nt][0] + bb.x, acc[mt][nt][1] + bb.y);
                float2 v1 = make_float2(acc[mt][nt][2] + bb.x, acc[mt][nt][3] + bb.y);
                *(float2*)(C + (size_t)r * N + c) = v0;
                *(float2*)(C + (size_t)(r + 8) * N + c) = v1;
            } else {
                C[(size_t)c * M + r]           = acc[mt][nt][0] + bb.x;
                C[(size_t)(c + 1) * M + r]     = acc[mt][nt][1] + bb.y;
                C[(size_t)c * M + r + 8]       = acc[mt][nt][2] + bb.x;
                C[(size_t)(c + 1) * M + r + 8] = acc[mt][nt][3] + bb.y;
            }
        }
    }
}

// ---------------------------------------------------------------------------
// RoPE (in-place on g_Q and g_K).
// ---------------------------------------------------------------------------
__global__ void rope_kernel(const float* __restrict__ cs, const float* __restrict__ sn)
{
    int idx = blockIdx.x * blockDim.x + threadIdx.x;
    const int total = SEQ * NH * (HD / 2);
    if (idx >= total) return;
    int j = idx % (HD / 2);
    int h = (idx / (HD / 2)) % NH;
    int s = idx / ((HD / 2) * NH);
    int base = s * DIM + h * HD;
    float c0 = cs[s * HD + j],      s0 = sn[s * HD + j];
    float c1 = cs[s * HD + j + 40], s1 = sn[s * HD + j + 40];
    {
        float x0 = g_Q[base + j], x1 = g_Q[base + j + 40];
        g_Q[base + j]      = x0 * c0 - x1 * s0;
        g_Q[base + j + 40] = x1 * c1 + x0 * s1;
    }
    {
        float x0 = g_K[base + j], x1 = g_K[base + j + 40];
        g_K[base + j]      = x0 * c0 - x1 * s0;
        g_K[base + j + 40] = x1 * c1 + x0 * s1;
    }
}

// ---------------------------------------------------------------------------
// Segmented flash attention on tensor cores (tf32 mma).
// Block = 64 queries x 1 head, 128 threads (4 warps, 16 q-rows each).
// S = Q K^T via m16n8k8; online softmax on C fragments; P staged via smem;
// O += P V via m16n8k8 with V pre-transposed globally ([DIM][SEQ]).
// Smem strides: 84 (Q/K: bank = 20g+tg, conflict-free), 68 (Vt/P: 4g+tg).
// ---------------------------------------------------------------------------
#define QS_STR 84
#define VT_STR 68
#define AT_KS  (64 * QS_STR)
#define AT_VT  (2 * 64 * QS_STR)
#define AT_PS  (AT_VT + 80 * VT_STR)
#define ATTN_SMEM ((AT_PS + 64 * VT_STR) * 4)   // 82176 B

__global__ __launch_bounds__(128)
void attn_mma(const int* __restrict__ cu, float* __restrict__ out)
{
    extern __shared__ float sm[];
    float* Qs = sm;
    float* Ks = sm + AT_KS;
    float* Vt = sm + AT_VT;
    float* Ps = sm + AT_PS;

    const int tid = threadIdx.x;
    const int warp = tid >> 5, lane = tid & 31;
    const int g = lane >> 2, tg = lane & 3;
    const int qb = blockIdx.x * 64;
    const int h  = blockIdx.y;
    const int m0 = warp * 16;

    int ks = 0, ke = SEQ;
#pragma unroll
    for (int i = 0; i < 4; i++)
        if (qb >= cu[i] && qb < cu[i + 1]) { ks = cu[i]; ke = cu[i + 1]; }

    const float scale = rsqrtf((float)HD);

    // Q tile: convert + scale once
    for (int i = tid; i < 64 * HD; i += 128) {
        int r = i / HD, d = i % HD;
        Qs[r * QS_STR + d] = f2tf32(g_Q[(size_t)(qb + r) * DIM + h * HD + d] * scale);
    }

    float mrow[2] = {-1e30f, -1e30f};
    float lrow[2] = {0.f, 0.f};
    float o[10][4];
#pragma unroll
    for (int nt = 0; nt < 10; nt++)
#pragma unroll
        for (int r = 0; r < 4; r++) o[nt][r] = 0.f;

    for (int kt = ks; kt < ke; kt += 64) {
        int kn = min(64, ke - kt);
        __syncthreads();
        for (int i = tid; i < 64 * HD; i += 128) {
            int r = i / HD, d = i % HD;
            Ks[r * QS_STR + d] = (r < kn) ? f2tf32(g_K[(size_t)(kt + r) * DIM + h * HD + d]) : 0.f;
        }
        for (int i = tid; i < HD * 64; i += 128) {
            int d = i >> 6, k = i & 63;
            Vt[d * VT_STR + k] = (k < kn) ? f2tf32(g_Vt[(size_t)(h * HD + d) * SEQ + kt + k]) : 0.f;
        }
        __syncthreads();

        // S = Q K^T  (warp rows m0..m0+15, all 64 cols = 8 n-tiles)
        float sacc[8][4];
#pragma unroll
        for (int nt = 0; nt < 8; nt++)
#pragma unroll
            for (int r = 0; r < 4; r++) sacc[nt][r] = 0.f;

#pragma unroll
        for (int ksp = 0; ksp < 10; ksp++) {
            const int k0 = ksp * 8;
            uint32_t af[4], bf[8][2];
            af[0] = __float_as_uint(Qs[(m0 + g) * QS_STR + k0 + tg]);
            af[1] = __float_as_uint(Qs[(m0 + 8 + g) * QS_STR + k0 + tg]);
            af[2] = __float_as_uint(Qs[(m0 + g) * QS_STR + k0 + tg + 4]);
            af[3] = __float_as_uint(Qs[(m0 + 8 + g) * QS_STR + k0 + tg + 4]);
#pragma unroll
            for (int nt = 0; nt < 8; nt++) {
                bf[nt][0] = __float_as_uint(Ks[(nt * 8 + g) * QS_STR + k0 + tg]);
                bf[nt][1] = __float_as_uint(Ks[(nt * 8 + g) * QS_STR + k0 + tg + 4]);
            }
#pragma unroll
            for (int nt = 0; nt < 8; nt++)
                mma_tf32(sacc[nt], af, bf[nt]);
        }

        if (kn < 64) {
#pragma unroll
            for (int nt = 0; nt < 8; nt++) {
                int c = nt * 8 + 2 * tg;
                if (c >= kn)     { sacc[nt][0] = -1e30f; sacc[nt][2] = -1e30f; }
                if (c + 1 >= kn) { sacc[nt][1] = -1e30f; sacc[nt][3] = -1e30f; }
            }
        }

        // Online softmax: row g (els 0,1) and row g+8 (els 2,3)
#pragma unroll
        for (int half = 0; half < 2; half++) {
            const int b = half * 2;
            float mloc = -1e30f;
#pragma unroll
            for (int nt = 0; nt < 8; nt++)
                mloc = fmaxf(mloc, fmaxf(sacc[nt][b], sacc[nt][b + 1]));
            mloc = fmaxf(mloc, __shfl_xor_sync(0xffffffffu, mloc, 1));
            mloc = fmaxf(mloc, __shfl_xor_sync(0xffffffffu, mloc, 2));
            float mn = fmaxf(mrow[half], mloc);
            float fac = __expf(mrow[half] - mn);
            mrow[half] = mn;
            float rs = 0.f;
#pragma unroll
            for (int nt = 0; nt < 8; nt++) {
                float p0 = __expf(sacc[nt][b] - mn);
                float p1 = __expf(sacc[nt][b + 1] - mn);
                sacc[nt][b] = p0; sacc[nt][b + 1] = p1;
                rs += p0 + p1;
            }
            rs += __shfl_xor_sync(0xffffffffu, rs, 1);
            rs += __shfl_xor_sync(0xffffffffu, rs, 2);
            lrow[half] = lrow[half] * fac + rs;
#pragma unroll
            for (int nt = 0; nt < 10; nt++) { o[nt][b] *= fac; o[nt][b + 1] *= fac; }
        }

        // Stage P (tf32) for the PV mma — warp-private rows, syncwarp suffices
#pragma unroll
        for (int nt = 0; nt < 8; nt++) {
            int c = nt * 8 + 2 * tg;
            Ps[(m0 + g) * VT_STR + c]         = f2tf32(sacc[nt][0]);
            Ps[(m0 + g) * VT_STR + c + 1]     = f2tf32(sacc[nt][1]);
            Ps[(m0 + 8 + g) * VT_STR + c]     = f2tf32(sacc[nt][2]);
            Ps[(m0 + 8 + g) * VT_STR + c + 1] = f2tf32(sacc[nt][3]);
        }
        __syncwarp();

        // O += P V  (10 n-tiles over d=80, 8 k-steps over 64 keys)
#pragma unroll
        for (int ksp = 0; ksp < 8; ksp++) {
            const int k0 = ksp * 8;
            uint32_t af[4], bf[10][2];
            af[0] = __float_as_uint(Ps[(m0 + g) * VT_STR + k0 + tg]);
            af[1] = __float_as_uint(Ps[(m0 + 8 + g) * VT_STR + k0 + tg]);
            af[2] = __float_as_uint(Ps[(m0 + g) * VT_STR + k0 + tg + 4]);
            af[3] = __float_as_uint(Ps[(m0 + 8 + g) * VT_STR + k0 + tg + 4]);
#pragma unroll
            for (int nt = 0; nt < 10; nt++) {
                bf[nt][0] = __float_as_uint(Vt[(nt * 8 + g) * VT_STR + k0 + tg]);
                bf[nt][1] = __float_as_uint(Vt[(nt * 8 + g) * VT_STR + k0 + tg + 4]);
            }
#pragma unroll
            for (int nt = 0; nt < 10; nt++)
                mma_tf32(o[nt], af, bf[nt]);
        }
    }

    const float inv0 = 1.f / lrow[0];
    const float inv1 = 1.f / lrow[1];
#pragma unroll
    for (int nt = 0; nt < 10; nt++) {
        int c = h * HD + nt * 8 + 2 * tg;
        *(float2*)(out + (size_t)(qb + m0 + g) * DIM + c) =
            make_float2(o[nt][0] * inv0, o[nt][1] * inv0);
        *(float2*)(out + (size_t)(qb + m0 + 8 + g) * DIM + c) =
            make_float2(o[nt][2] * inv1, o[nt][3] * inv1);
    }
}

// ---------------------------------------------------------------------------
extern "C" void kernel_launch(void* const* d_in, const int* in_sizes, int n_in,
                              void* d_out, int out_size)
{
    const float* X  = (const float*)d_in[0];
    const float* Wq = (const float*)d_in[1];
    const float* bq = (const float*)d_in[2];
    const float* Wk = (const float*)d_in[3];
    const float* bk = (const float*)d_in[4];
    const float* Wv = (const float*)d_in[5];
    const float* bv = (const float*)d_in[6];
    const float* Wo = (const float*)d_in[7];
    const float* bo = (const float*)d_in[8];
    const float* cs = (const float*)d_in[9];
    const float* sn = (const float*)d_in[10];
    const int*   cu = (const int*)d_in[11];
    float* out = (float*)d_out;

    void *pQ, *pK, *pVt, *pA;
    cudaGetSymbolAddress(&pQ, g_Q);
    cudaGetSymbolAddress(&pK, g_K);
    cudaGetSymbolAddress(&pVt, g_Vt);
    cudaGetSymbolAddress(&pA, g_A);

    cudaFuncSetAttribute(gemm_tf32_pipe<false>,
                         cudaFuncAttributeMaxDynamicSharedMemorySize, GEMM_SMEM);
    cudaFuncSetAttribute(gemm_tf32_pipe<true>,
                         cudaFuncAttributeMaxDynamicSharedMemorySize, GEMM_SMEM);
    cudaFuncSetAttribute(attn_mma,
                         cudaFuncAttributeMaxDynamicSharedMemorySize, ATTN_SMEM);

    dim3 gg(DIM / BN, SEQ / BM);  // (10, 16)
    dim3 gb(256);

    gemm_tf32_pipe<false><<<gg, gb, GEMM_SMEM>>>(X, Wq, bq, (float*)pQ, SEQ, DIM, DIM);
    gemm_tf32_pipe<false><<<gg, gb, GEMM_SMEM>>>(X, Wk, bk, (float*)pK, SEQ, DIM, DIM);
    gemm_tf32_pipe<true ><<<gg, gb, GEMM_SMEM>>>(X, Wv, bv, (float*)pVt, SEQ, DIM, DIM);

    int rope_total = SEQ * NH * (HD / 2);
    rope_kernel<<<(rope_total + 255) / 256, 256>>>(cs, sn);

    dim3 ga(SEQ / 64, NH);        // (32, 16)
    attn_mma<<<ga, 128, ATTN_SMEM>>>(cu, (float*)pA);

    gemm_tf32_pipe<false><<<gg, gb, GEMM_SMEM>>>((const float*)pA, Wo, bo, out, SEQ, DIM, DIM);
}

// round 4
// speedup vs baseline: 3.4259x; 1.5656x over previous
#include <cuda_runtime.h>
#include <math.h>
#include <stdint.h>

#define SEQ 2048
#define DIM 1280
#define NH  16
#define HD  80

// Scratch (device globals)
__device__ float g_Q[SEQ * DIM];
__device__ float g_K[SEQ * DIM];
__device__ float g_Vt[SEQ * DIM];   // V transposed: [DIM][SEQ]
__device__ float g_A[SEQ * DIM];
__device__ float g_Xr[SEQ * DIM];   // tf32-rounded hidden_states
__device__ float g_Wr[DIM * DIM];   // tf32-rounded weight (reused per GEMM)

__device__ __forceinline__ float f2tf32(float x) {
    uint32_t u;
    asm("cvt.rna.tf32.f32 %0, %1;" : "=r"(u) : "f"(x));
    return __uint_as_float(u);
}

__device__ __forceinline__ void mma_tf32(float* c, const uint32_t* a, const uint32_t* b) {
    asm("mma.sync.aligned.m16n8k8.row.col.f32.tf32.tf32.f32 "
        "{%0,%1,%2,%3}, {%4,%5,%6,%7}, {%8,%9}, {%0,%1,%2,%3};"
        : "+f"(c[0]), "+f"(c[1]), "+f"(c[2]), "+f"(c[3])
        : "r"(a[0]), "r"(a[1]), "r"(a[2]), "r"(a[3]), "r"(b[0]), "r"(b[1]));
}

// ---------------------------------------------------------------------------
// Elementwise tf32 rounding pass (float4 vectorized).
// ---------------------------------------------------------------------------
__global__ void cvt_tf32_pass(const float* __restrict__ x, float* __restrict__ y, int n4)
{
    int i = blockIdx.x * blockDim.x + threadIdx.x;
    if (i >= n4) return;
    float4 v = ((const float4*)x)[i];
    ((float4*)y)[i] = make_float4(f2tf32(v.x), f2tf32(v.y), f2tf32(v.z), f2tf32(v.w));
}

// ---------------------------------------------------------------------------
// TF32 GEMM (NT), 2-stage cp.async pipeline, BALANCED GRID.
// C[M,N] = A[M,K] B[N,K]^T + bias.  TRANS: store C transposed [N][M].
// BM=128, BN=160 -> grid (1280/160=8, 2048/128=16) = 128 CTAs, 1 per SM.
// 256 thr (2x4 warps), warp tile 64x40. Operands pre-rounded to tf32 format
// in global memory, so the mainloop has zero cvt instructions.
// ---------------------------------------------------------------------------
#define BM 128
#define BN 160
#define BK 32
#define SST 36
#define GEMM_SMEM ((2 * BM * SST + 2 * BN * SST) * 4)   // 82944 B

__device__ __forceinline__ void cp16(uint32_t dst, const void* src) {
    asm volatile("cp.async.cg.shared.global [%0], [%1], 16;\n" :: "r"(dst), "l"(src));
}

template<bool TRANS>
__global__ __launch_bounds__(256, 1)
void gemm_tf32_pipe(const float* __restrict__ A, const float* __restrict__ B,
                    const float* __restrict__ bias, float* __restrict__ C,
                    int M, int N, int K)
{
    extern __shared__ float sm[];
    float* As = sm;                    // [2][BM*SST]
    float* Bs = sm + 2 * BM * SST;     // [2][BN*SST]

    const int tid = threadIdx.x;
    const int m0 = blockIdx.y * BM;
    const int n0 = blockIdx.x * BN;

    const int warp = tid >> 5, lane = tid & 31;
    const int wm = warp >> 2, wn = warp & 3;     // 2 x 4 warps
    const int g = lane >> 2, tg = lane & 3;

    const uint32_t sA = (uint32_t)__cvta_generic_to_shared(As);
    const uint32_t sB = (uint32_t)__cvta_generic_to_shared(Bs);

    float acc[4][5][4];
#pragma unroll
    for (int mt = 0; mt < 4; mt++)
#pragma unroll
        for (int nt = 0; nt < 5; nt++)
#pragma unroll
            for (int r = 0; r < 4; r++) acc[mt][nt][r] = 0.f;

    const int T = K / BK;   // 40

    auto issue = [&](int stage, int kt) {
#pragma unroll
        for (int t = 0; t < 4; t++) {            // A: 128 rows x 32 k
            int idx = tid + t * 256;
            int r = idx >> 3;
            int kc = (idx & 7) << 2;
            uint32_t off = (uint32_t)(stage * BM * SST + r * SST + kc) * 4u;
            cp16(sA + off, A + (size_t)(m0 + r) * K + kt + kc);
        }
#pragma unroll
        for (int t = 0; t < 5; t++) {            // B: 160 rows x 32 k
            int idx = tid + t * 256;
            int r = idx >> 3;
            int kc = (idx & 7) << 2;
            uint32_t off = (uint32_t)(stage * BN * SST + r * SST + kc) * 4u;
            cp16(sB + off, B + (size_t)(n0 + r) * K + kt + kc);
        }
        asm volatile("cp.async.commit_group;\n");
    };

    issue(0, 0);

    for (int ti = 0; ti < T; ti++) {
        if (ti + 1 < T) {
            issue((ti + 1) & 1, (ti + 1) * BK);
            asm volatile("cp.async.wait_group 1;\n");
        } else {
            asm volatile("cp.async.wait_group 0;\n");
        }
        __syncthreads();

        const float* Asr = As + (ti & 1) * BM * SST;
        const float* Bsr = Bs + (ti & 1) * BN * SST;

#pragma unroll
        for (int ks = 0; ks < 4; ks++) {
            const int k0 = ks * 8;
            uint32_t af[4][4], bf[5][2];
#pragma unroll
            for (int mt = 0; mt < 4; mt++) {
                int r = wm * 64 + mt * 16 + g;
                af[mt][0] = __float_as_uint(Asr[r * SST + k0 + tg]);
                af[mt][1] = __float_as_uint(Asr[(r + 8) * SST + k0 + tg]);
                af[mt][2] = __float_as_uint(Asr[r * SST + k0 + tg + 4]);
                af[mt][3] = __float_as_uint(Asr[(r + 8) * SST + k0 + tg + 4]);
            }
#pragma unroll
            for (int nt = 0; nt < 5; nt++) {
                int c = wn * 40 + nt * 8 + g;
                bf[nt][0] = __float_as_uint(Bsr[c * SST + k0 + tg]);
                bf[nt][1] = __float_as_uint(Bsr[c * SST + k0 + tg + 4]);
            }
#pragma unroll
            for (int mt = 0; mt < 4; mt++)
#pragma unroll
                for (int nt = 0; nt < 5; nt++)
                    mma_tf32(acc[mt][nt], af[mt], bf[nt]);
        }
        __syncthreads();
    }

#pragma unroll
    for (int mt = 0; mt < 4; mt++) {
#pragma unroll
        for (int nt = 0; nt < 5; nt++) {
            int r = m0 + wm * 64 + mt * 16 + g;
            int c = n0 + wn * 40 + nt * 8 + 2 * tg;
            float2 bb = *(const float2*)(bias + c);
            if (!TRANS) {
                float2 v0 = make_float2(acc[mt][nt][0] + bb.x, acc[mt][nt][1] + bb.y);
                float2 v1 = make_float2(acc[mt][nt][2] + bb.x, acc[mt][nt][3] + bb.y);
                *(float2*)(C + (size_t)r * N + c) = v0;
                *(float2*)(C + (size_t)(r + 8) * N + c) = v1;
            } else {
                C[(size_t)c * M + r]           = acc[mt][nt][0] + bb.x;
                C[(size_t)(c + 1) * M + r]     = acc[mt][nt][1] + bb.y;
                C[(size_t)c * M + r + 8]       = acc[mt][nt][2] + bb.x;
                C[(size_t)(c + 1) * M + r + 8] = acc[mt][nt][3] + bb.y;
            }
        }
    }
}

// ---------------------------------------------------------------------------
// RoPE (in-place on g_Q and g_K).
// ---------------------------------------------------------------------------
__global__ void rope_kernel(const float* __restrict__ cs, const float* __restrict__ sn)
{
    int idx = blockIdx.x * blockDim.x + threadIdx.x;
    const int total = SEQ * NH * (HD / 2);
    if (idx >= total) return;
    int j = idx % (HD / 2);
    int h = (idx / (HD / 2)) % NH;
    int s = idx / ((HD / 2) * NH);
    int base = s * DIM + h * HD;
    float c0 = cs[s * HD + j],      s0 = sn[s * HD + j];
    float c1 = cs[s * HD + j + 40], s1 = sn[s * HD + j + 40];
    {
        float x0 = g_Q[base + j], x1 = g_Q[base + j + 40];
        g_Q[base + j]      = x0 * c0 - x1 * s0;
        g_Q[base + j + 40] = x1 * c1 + x0 * s1;
    }
    {
        float x0 = g_K[base + j], x1 = g_K[base + j + 40];
        g_K[base + j]      = x0 * c0 - x1 * s0;
        g_K[base + j + 40] = x1 * c1 + x0 * s1;
    }
}

// ---------------------------------------------------------------------------
// PERSISTENT segmented flash attention on tensor cores (tf32 mma).
// grid = 296 CTAs (148 SMs x occ 2), 128 thr (4 warps). Each CTA loops over
// uniform work items (64-query tile, head); 512 items, stride 296.
// Output stores are pre-rounded to tf32 for the O-projection GEMM.
// ---------------------------------------------------------------------------
#define ATT_GRID 296
#define QS_STR 84
#define VT_STR 68
#define AT_KS  (64 * QS_STR)
#define AT_VT  (2 * 64 * QS_STR)
#define AT_PS  (AT_VT + 80 * VT_STR)
#define ATTN_SMEM ((AT_PS + 64 * VT_STR) * 4)   // 82176 B

__global__ __launch_bounds__(128)
void attn_mma(const int* __restrict__ cu, float* __restrict__ out)
{
    extern __shared__ float sm[];
    float* Qs = sm;
    float* Ks = sm + AT_KS;
    float* Vt = sm + AT_VT;
    float* Ps = sm + AT_PS;

    const int tid = threadIdx.x;
    const int warp = tid >> 5, lane = tid & 31;
    const int g = lane >> 2, tg = lane & 3;
    const int m0 = warp * 16;

    for (int item = blockIdx.x; item < (SEQ / 64) * NH; item += ATT_GRID) {
        const int qb = (item >> 4) * 64;
        const int h  = item & 15;

        int ks = 0, ke = SEQ;
#pragma unroll
        for (int i = 0; i < 4; i++)
            if (qb >= cu[i] && qb < cu[i + 1]) { ks = cu[i]; ke = cu[i + 1]; }

        const float scale = rsqrtf((float)HD);

        __syncthreads();   // protect Qs against previous item's readers
        for (int i = tid; i < 64 * HD; i += 128) {
            int r = i / HD, d = i % HD;
            Qs[r * QS_STR + d] = f2tf32(g_Q[(size_t)(qb + r) * DIM + h * HD + d] * scale);
        }

        float mrow[2] = {-1e30f, -1e30f};
        float lrow[2] = {0.f, 0.f};
        float o[10][4];
#pragma unroll
        for (int nt = 0; nt < 10; nt++)
#pragma unroll
            for (int r = 0; r < 4; r++) o[nt][r] = 0.f;

        for (int kt = ks; kt < ke; kt += 64) {
            int kn = min(64, ke - kt);
            __syncthreads();
            for (int i = tid; i < 64 * HD; i += 128) {
                int r = i / HD, d = i % HD;
                Ks[r * QS_STR + d] = (r < kn) ? f2tf32(g_K[(size_t)(kt + r) * DIM + h * HD + d]) : 0.f;
            }
            for (int i = tid; i < HD * 64; i += 128) {
                int d = i >> 6, k = i & 63;
                Vt[d * VT_STR + k] = (k < kn) ? f2tf32(g_Vt[(size_t)(h * HD + d) * SEQ + kt + k]) : 0.f;
            }
            __syncthreads();

            float sacc[8][4];
#pragma unroll
            for (int nt = 0; nt < 8; nt++)
#pragma unroll
                for (int r = 0; r < 4; r++) sacc[nt][r] = 0.f;

#pragma unroll
            for (int ksp = 0; ksp < 10; ksp++) {
                const int k0 = ksp * 8;
                uint32_t af[4], bf[8][2];
                af[0] = __float_as_uint(Qs[(m0 + g) * QS_STR + k0 + tg]);
                af[1] = __float_as_uint(Qs[(m0 + 8 + g) * QS_STR + k0 + tg]);
                af[2] = __float_as_uint(Qs[(m0 + g) * QS_STR + k0 + tg + 4]);
                af[3] = __float_as_uint(Qs[(m0 + 8 + g) * QS_STR + k0 + tg + 4]);
#pragma unroll
                for (int nt = 0; nt < 8; nt++) {
                    bf[nt][0] = __float_as_uint(Ks[(nt * 8 + g) * QS_STR + k0 + tg]);
                    bf[nt][1] = __float_as_uint(Ks[(nt * 8 + g) * QS_STR + k0 + tg + 4]);
                }
#pragma unroll
                for (int nt = 0; nt < 8; nt++)
                    mma_tf32(sacc[nt], af, bf[nt]);
            }

            if (kn < 64) {
#pragma unroll
                for (int nt = 0; nt < 8; nt++) {
                    int c = nt * 8 + 2 * tg;
                    if (c >= kn)     { sacc[nt][0] = -1e30f; sacc[nt][2] = -1e30f; }
                    if (c + 1 >= kn) { sacc[nt][1] = -1e30f; sacc[nt][3] = -1e30f; }
                }
            }

#pragma unroll
            for (int half = 0; half < 2; half++) {
                const int b = half * 2;
                float mloc = -1e30f;
#pragma unroll
                for (int nt = 0; nt < 8; nt++)
                    mloc = fmaxf(mloc, fmaxf(sacc[nt][b], sacc[nt][b + 1]));
                mloc = fmaxf(mloc, __shfl_xor_sync(0xffffffffu, mloc, 1));
                mloc = fmaxf(mloc, __shfl_xor_sync(0xffffffffu, mloc, 2));
                float mn = fmaxf(mrow[half], mloc);
                float fac = __expf(mrow[half] - mn);
                mrow[half] = mn;
                float rs = 0.f;
#pragma unroll
                for (int nt = 0; nt < 8; nt++) {
                    float p0 = __expf(sacc[nt][b] - mn);
                    float p1 = __expf(sacc[nt][b + 1] - mn);
                    sacc[nt][b] = p0; sacc[nt][b + 1] = p1;
                    rs += p0 + p1;
                }
                rs += __shfl_xor_sync(0xffffffffu, rs, 1);
                rs += __shfl_xor_sync(0xffffffffu, rs, 2);
                lrow[half] = lrow[half] * fac + rs;
#pragma unroll
                for (int nt = 0; nt < 10; nt++) { o[nt][b] *= fac; o[nt][b + 1] *= fac; }
            }

            // Stage P (tf32) — warp-private rows
#pragma unroll
            for (int nt = 0; nt < 8; nt++) {
                int c = nt * 8 + 2 * tg;
                Ps[(m0 + g) * VT_STR + c]         = f2tf32(sacc[nt][0]);
                Ps[(m0 + g) * VT_STR + c + 1]     = f2tf32(sacc[nt][1]);
                Ps[(m0 + 8 + g) * VT_STR + c]     = f2tf32(sacc[nt][2]);
                Ps[(m0 + 8 + g) * VT_STR + c + 1] = f2tf32(sacc[nt][3]);
            }
            __syncwarp();

#pragma unroll
            for (int ksp = 0; ksp < 8; ksp++) {
                const int k0 = ksp * 8;
                uint32_t af[4], bf[10][2];
                af[0] = __float_as_uint(Ps[(m0 + g) * VT_STR + k0 + tg]);
                af[1] = __float_as_uint(Ps[(m0 + 8 + g) * VT_STR + k0 + tg]);
                af[2] = __float_as_uint(Ps[(m0 + g) * VT_STR + k0 + tg + 4]);
                af[3] = __float_as_uint(Ps[(m0 + 8 + g) * VT_STR + k0 + tg + 4]);
#pragma unroll
                for (int nt = 0; nt < 10; nt++) {
                    bf[nt][0] = __float_as_uint(Vt[(nt * 8 + g) * VT_STR + k0 + tg]);
                    bf[nt][1] = __float_as_uint(Vt[(nt * 8 + g) * VT_STR + k0 + tg + 4]);
                }
#pragma unroll
                for (int nt = 0; nt < 10; nt++)
                    mma_tf32(o[nt], af, bf[nt]);
            }
        }

        const float inv0 = 1.f / lrow[0];
        const float inv1 = 1.f / lrow[1];
#pragma unroll
        for (int nt = 0; nt < 10; nt++) {
            int c = h * HD + nt * 8 + 2 * tg;
            *(float2*)(out + (size_t)(qb + m0 + g) * DIM + c) =
                make_float2(f2tf32(o[nt][0] * inv0), f2tf32(o[nt][1] * inv0));
            *(float2*)(out + (size_t)(qb + m0 + 8 + g) * DIM + c) =
                make_float2(f2tf32(o[nt][2] * inv1), f2tf32(o[nt][3] * inv1));
        }
    }
}

// ---------------------------------------------------------------------------
extern "C" void kernel_launch(void* const* d_in, const int* in_sizes, int n_in,
                              void* d_out, int out_size)
{
    const float* X  = (const float*)d_in[0];
    const float* Wq = (const float*)d_in[1];
    const float* bq = (const float*)d_in[2];
    const float* Wk = (const float*)d_in[3];
    const float* bk = (const float*)d_in[4];
    const float* Wv = (const float*)d_in[5];
    const float* bv = (const float*)d_in[6];
    const float* Wo = (const float*)d_in[7];
    const float* bo = (const float*)d_in[8];
    const float* cs = (const float*)d_in[9];
    const float* sn = (const float*)d_in[10];
    const int*   cu = (const int*)d_in[11];
    float* out = (float*)d_out;

    void *pQ, *pK, *pVt, *pA, *pXr, *pWr;
    cudaGetSymbolAddress(&pQ, g_Q);
    cudaGetSymbolAddress(&pK, g_K);
    cudaGetSymbolAddress(&pVt, g_Vt);
    cudaGetSymbolAddress(&pA, g_A);
    cudaGetSymbolAddress(&pXr, g_Xr);
    cudaGetSymbolAddress(&pWr, g_Wr);

    cudaFuncSetAttribute(gemm_tf32_pipe<false>,
                         cudaFuncAttributeMaxDynamicSharedMemorySize, GEMM_SMEM);
    cudaFuncSetAttribute(gemm_tf32_pipe<true>,
                         cudaFuncAttributeMaxDynamicSharedMemorySize, GEMM_SMEM);
    cudaFuncSetAttribute(attn_mma,
                         cudaFuncAttributeMaxDynamicSharedMemorySize, ATTN_SMEM);

    const int nX4 = SEQ * DIM / 4;     // 655360 floats -> 163840 float4
    const int nW4 = DIM * DIM / 4;
    dim3 gg(DIM / BN, SEQ / BM);       // (8, 16) = 128 CTAs
    dim3 gb(256);

    cvt_tf32_pass<<<(nX4 + 255) / 256, 256>>>(X, (float*)pXr, nX4);

    cvt_tf32_pass<<<(nW4 + 255) / 256, 256>>>(Wq, (float*)pWr, nW4);
    gemm_tf32_pipe<false><<<gg, gb, GEMM_SMEM>>>((const float*)pXr, (const float*)pWr, bq, (float*)pQ, SEQ, DIM, DIM);

    cvt_tf32_pass<<<(nW4 + 255) / 256, 256>>>(Wk, (float*)pWr, nW4);
    gemm_tf32_pipe<false><<<gg, gb, GEMM_SMEM>>>((const float*)pXr, (const float*)pWr, bk, (float*)pK, SEQ, DIM, DIM);

    cvt_tf32_pass<<<(nW4 + 255) / 256, 256>>>(Wv, (float*)pWr, nW4);
    gemm_tf32_pipe<true ><<<gg, gb, GEMM_SMEM>>>((const float*)pXr, (const float*)pWr, bv, (float*)pVt, SEQ, DIM, DIM);

    int rope_total = SEQ * NH * (HD / 2);
    rope_kernel<<<(rope_total + 255) / 256, 256>>>(cs, sn);

    attn_mma<<<ATT_GRID, 128, ATTN_SMEM>>>(cu, (float*)pA);

    cvt_tf32_pass<<<(nW4 + 255) / 256, 256>>>(Wo, (float*)pWr, nW4);
    gemm_tf32_pipe<false><<<gg, gb, GEMM_SMEM>>>((const float*)pA, (const float*)pWr, bo, out, SEQ, DIM, DIM);
}

// round 5
// speedup vs baseline: 4.6324x; 1.3522x over previous
#include <cuda_runtime.h>
#include <math.h>
#include <stdint.h>

#define SEQ 2048
#define DIM 1280
#define NH  16
#define HD  80

// Scratch (device globals)
__device__ float g_Q[SEQ * DIM];
__device__ float g_K[SEQ * DIM];
__device__ float g_Vt[SEQ * DIM];    // V transposed: [DIM][SEQ], tf32-rounded
__device__ float g_A[SEQ * DIM];
__device__ float g_Xr[SEQ * DIM];    // tf32-rounded hidden_states
__device__ float g_Wqr[DIM * DIM];
__device__ float g_Wkr[DIM * DIM];
__device__ float g_Wvr[DIM * DIM];
__device__ float g_Wor[DIM * DIM];

__device__ __forceinline__ float f2tf32(float x) {
    uint32_t u;
    asm("cvt.rna.tf32.f32 %0, %1;" : "=r"(u) : "f"(x));
    return __uint_as_float(u);
}

__device__ __forceinline__ void mma_tf32(float* c, const uint32_t* a, const uint32_t* b) {
    asm("mma.sync.aligned.m16n8k8.row.col.f32.tf32.tf32.f32 "
        "{%0,%1,%2,%3}, {%4,%5,%6,%7}, {%8,%9}, {%0,%1,%2,%3};"
        : "+f"(c[0]), "+f"(c[1]), "+f"(c[2]), "+f"(c[3])
        : "r"(a[0]), "r"(a[1]), "r"(a[2]), "r"(a[3]), "r"(b[0]), "r"(b[1]));
}

__device__ __forceinline__ void cp16(uint32_t dst, const void* src) {
    asm volatile("cp.async.cg.shared.global [%0], [%1], 16;\n" :: "r"(dst), "l"(src));
}
// zfill form: copies `bytes` (0..16) from src, zero-fills the rest of 16B.
__device__ __forceinline__ void cp16z(uint32_t dst, const void* src, int bytes) {
    asm volatile("cp.async.cg.shared.global [%0], [%1], 16, %2;\n"
                 :: "r"(dst), "l"(src), "r"(bytes));
}

// ---------------------------------------------------------------------------
// Fused tf32 rounding for X + all 4 weights (one launch).
// ---------------------------------------------------------------------------
#define NX4 (SEQ * DIM / 4)
#define NW4 (DIM * DIM / 4)
__global__ void cvt_all(const float* __restrict__ X,
                        const float* __restrict__ Wq, const float* __restrict__ Wk,
                        const float* __restrict__ Wv, const float* __restrict__ Wo)
{
    int i = blockIdx.x * blockDim.x + threadIdx.x;
    const float* src; float* dst; int off;
    if (i < NX4)               { src = X;  dst = g_Xr;  off = i; }
    else if (i < NX4 + NW4)    { src = Wq; dst = g_Wqr; off = i - NX4; }
    else if (i < NX4 + 2*NW4)  { src = Wk; dst = g_Wkr; off = i - NX4 - NW4; }
    else if (i < NX4 + 3*NW4)  { src = Wv; dst = g_Wvr; off = i - NX4 - 2*NW4; }
    else if (i < NX4 + 4*NW4)  { src = Wo; dst = g_Wor; off = i - NX4 - 3*NW4; }
    else return;
    float4 v = ((const float4*)src)[off];
    ((float4*)dst)[off] = make_float4(f2tf32(v.x), f2tf32(v.y), f2tf32(v.z), f2tf32(v.w));
}

// ---------------------------------------------------------------------------
// TF32 GEMM (NT), 2-stage cp.async pipeline, balanced grid (128 CTAs).
// TRANS epilogue also rounds output to tf32 (feeds attention V operand).
// ---------------------------------------------------------------------------
#define BM 128
#define BN 160
#define BK 32
#define SST 36
#define GEMM_SMEM ((2 * BM * SST + 2 * BN * SST) * 4)   // 82944 B

template<bool TRANS>
__global__ __launch_bounds__(256, 1)
void gemm_tf32_pipe(const float* __restrict__ A, const float* __restrict__ B,
                    const float* __restrict__ bias, float* __restrict__ C,
                    int M, int N, int K)
{
    extern __shared__ float sm[];
    float* As = sm;
    float* Bs = sm + 2 * BM * SST;

    const int tid = threadIdx.x;
    const int m0 = blockIdx.y * BM;
    const int n0 = blockIdx.x * BN;

    const int warp = tid >> 5, lane = tid & 31;
    const int wm = warp >> 2, wn = warp & 3;
    const int g = lane >> 2, tg = lane & 3;

    const uint32_t sA = (uint32_t)__cvta_generic_to_shared(As);
    const uint32_t sB = (uint32_t)__cvta_generic_to_shared(Bs);

    float acc[4][5][4];
#pragma unroll
    for (int mt = 0; mt < 4; mt++)
#pragma unroll
        for (int nt = 0; nt < 5; nt++)
#pragma unroll
            for (int r = 0; r < 4; r++) acc[mt][nt][r] = 0.f;

    const int T = K / BK;

    auto issue = [&](int stage, int kt) {
#pragma unroll
        for (int t = 0; t < 4; t++) {
            int idx = tid + t * 256;
            int r = idx >> 3;
            int kc = (idx & 7) << 2;
            uint32_t off = (uint32_t)(stage * BM * SST + r * SST + kc) * 4u;
            cp16(sA + off, A + (size_t)(m0 + r) * K + kt + kc);
        }
#pragma unroll
        for (int t = 0; t < 5; t++) {
            int idx = tid + t * 256;
            int r = idx >> 3;
            int kc = (idx & 7) << 2;
            uint32_t off = (uint32_t)(stage * BN * SST + r * SST + kc) * 4u;
            cp16(sB + off, B + (size_t)(n0 + r) * K + kt + kc);
        }
        asm volatile("cp.async.commit_group;\n");
    };

    issue(0, 0);

    for (int ti = 0; ti < T; ti++) {
        if (ti + 1 < T) {
            issue((ti + 1) & 1, (ti + 1) * BK);
            asm volatile("cp.async.wait_group 1;\n");
        } else {
            asm volatile("cp.async.wait_group 0;\n");
        }
        __syncthreads();

        const float* Asr = As + (ti & 1) * BM * SST;
        const float* Bsr = Bs + (ti & 1) * BN * SST;

#pragma unroll
        for (int ks = 0; ks < 4; ks++) {
            const int k0 = ks * 8;
            uint32_t af[4][4], bf[5][2];
#pragma unroll
            for (int mt = 0; mt < 4; mt++) {
                int r = wm * 64 + mt * 16 + g;
                af[mt][0] = __float_as_uint(Asr[r * SST + k0 + tg]);
                af[mt][1] = __float_as_uint(Asr[(r + 8) * SST + k0 + tg]);
                af[mt][2] = __float_as_uint(Asr[r * SST + k0 + tg + 4]);
                af[mt][3] = __float_as_uint(Asr[(r + 8) * SST + k0 + tg + 4]);
            }
#pragma unroll
            for (int nt = 0; nt < 5; nt++) {
                int c = wn * 40 + nt * 8 + g;
                bf[nt][0] = __float_as_uint(Bsr[c * SST + k0 + tg]);
                bf[nt][1] = __float_as_uint(Bsr[c * SST + k0 + tg + 4]);
            }
#pragma unroll
            for (int mt = 0; mt < 4; mt++)
#pragma unroll
                for (int nt = 0; nt < 5; nt++)
                    mma_tf32(acc[mt][nt], af[mt], bf[nt]);
        }
        __syncthreads();
    }

#pragma unroll
    for (int mt = 0; mt < 4; mt++) {
#pragma unroll
        for (int nt = 0; nt < 5; nt++) {
            int r = m0 + wm * 64 + mt * 16 + g;
            int c = n0 + wn * 40 + nt * 8 + 2 * tg;
            float2 bb = *(const float2*)(bias + c);
            if (!TRANS) {
                float2 v0 = make_float2(acc[mt][nt][0] + bb.x, acc[mt][nt][1] + bb.y);
                float2 v1 = make_float2(acc[mt][nt][2] + bb.x, acc[mt][nt][3] + bb.y);
                *(float2*)(C + (size_t)r * N + c) = v0;
                *(float2*)(C + (size_t)(r + 8) * N + c) = v1;
            } else {
                C[(size_t)c * M + r]           = f2tf32(acc[mt][nt][0] + bb.x);
                C[(size_t)(c + 1) * M + r]     = f2tf32(acc[mt][nt][1] + bb.y);
                C[(size_t)c * M + r + 8]       = f2tf32(acc[mt][nt][2] + bb.x);
                C[(size_t)(c + 1) * M + r + 8] = f2tf32(acc[mt][nt][3] + bb.y);
            }
        }
    }
}

// ---------------------------------------------------------------------------
// RoPE in place on g_Q / g_K. Q additionally pre-scaled by 1/sqrt(hd).
// Both outputs tf32-rounded so attention fills are pure copies.
// ---------------------------------------------------------------------------
__global__ void rope_kernel(const float* __restrict__ cs, const float* __restrict__ sn)
{
    int idx = blockIdx.x * blockDim.x + threadIdx.x;
    const int total = SEQ * NH * (HD / 2);
    if (idx >= total) return;
    int j = idx % (HD / 2);
    int h = (idx / (HD / 2)) % NH;
    int s = idx / ((HD / 2) * NH);
    int base = s * DIM + h * HD;
    const float scale = rsqrtf((float)HD);
    float c0 = cs[s * HD + j],      s0 = sn[s * HD + j];
    float c1 = cs[s * HD + j + 40], s1 = sn[s * HD + j + 40];
    {
        float x0 = g_Q[base + j], x1 = g_Q[base + j + 40];
        g_Q[base + j]      = f2tf32((x0 * c0 - x1 * s0) * scale);
        g_Q[base + j + 40] = f2tf32((x1 * c1 + x0 * s1) * scale);
    }
    {
        float x0 = g_K[base + j], x1 = g_K[base + j + 40];
        g_K[base + j]      = f2tf32(x0 * c0 - x1 * s0);
        g_K[base + j + 40] = f2tf32(x1 * c1 + x0 * s1);
    }
}

// ---------------------------------------------------------------------------
// Persistent segmented flash attention, tf32 mma, cp.async-pipelined fills.
// grid = 296 (148 SM x occ 2), 128 thr. V_i loads during S_i; K_{i+1} loads
// during softmax+PV_i. All inputs pre-rounded -> fills are raw 16B copies.
// ---------------------------------------------------------------------------
#define ATT_GRID 296
#define QS_STR 84
#define VT_STR 68
#define AT_KS  (64 * QS_STR)
#define AT_VT  (2 * 64 * QS_STR)
#define AT_PS  (AT_VT + 80 * VT_STR)
#define ATTN_SMEM ((AT_PS + 64 * VT_STR) * 4)   // 82176 B

__global__ __launch_bounds__(128)
void attn_mma(const int* __restrict__ cu, float* __restrict__ out)
{
    extern __shared__ float sm[];
    float* Qs = sm;
    float* Ks = sm + AT_KS;
    float* Vt = sm + AT_VT;
    float* Ps = sm + AT_PS;

    const uint32_t sQ = (uint32_t)__cvta_generic_to_shared(Qs);
    const uint32_t sK = (uint32_t)__cvta_generic_to_shared(Ks);
    const uint32_t sV = (uint32_t)__cvta_generic_to_shared(Vt);

    const int tid = threadIdx.x;
    const int warp = tid >> 5, lane = tid & 31;
    const int g = lane >> 2, tg = lane & 3;
    const int m0 = warp * 16;

    // Fill helpers: 1280 16B-chunks each, 10 per thread.
    // Q/K: row r (64), 20 chunks per row (80 floats). V: row d (80), 16 chunks.
    auto issueQ = [&](int qb) {
#pragma unroll
        for (int t = 0; t < 10; t++) {
            int idx = tid + t * 128;
            int r = idx / 20, dc = (idx % 20) * 4;
            cp16(sQ + (uint32_t)(r * QS_STR + dc) * 4u,
                 g_Q + (size_t)(qb + r) * DIM + (blockIdx.y /*unused*/, 0) + dc);
        }
    };
    (void)issueQ;

    for (int item = blockIdx.x; item < (SEQ / 64) * NH; item += ATT_GRID) {
        const int qb = (item >> 4) * 64;
        const int h  = item & 15;

        int ks = 0, ke = SEQ;
#pragma unroll
        for (int i = 0; i < 4; i++)
            if (qb >= cu[i] && qb < cu[i + 1]) { ks = cu[i]; ke = cu[i + 1]; }

        __syncthreads();   // prior item's smem readers done

        // Q fill (group) + first K fill (group)
#pragma unroll
        for (int t = 0; t < 10; t++) {
            int idx = tid + t * 128;
            int r = idx / 20, dc = (idx % 20) * 4;
            cp16(sQ + (uint32_t)(r * QS_STR + dc) * 4u,
                 g_Q + (size_t)(qb + r) * DIM + h * HD + dc);
        }
        asm volatile("cp.async.commit_group;\n");
        {
            int kn0 = min(64, ke - ks);
#pragma unroll
            for (int t = 0; t < 10; t++) {
                int idx = tid + t * 128;
                int r = idx / 20, dc = (idx % 20) * 4;
                int srow = (r < kn0) ? (ks + r) : ks;
                cp16z(sK + (uint32_t)(r * QS_STR + dc) * 4u,
                      g_K + (size_t)srow * DIM + h * HD + dc, (r < kn0) ? 16 : 0);
            }
            asm volatile("cp.async.commit_group;\n");
        }

        float mrow[2] = {-1e30f, -1e30f};
        float lrow[2] = {0.f, 0.f};
        float o[10][4];
#pragma unroll
        for (int nt = 0; nt < 10; nt++)
#pragma unroll
            for (int r = 0; r < 4; r++) o[nt][r] = 0.f;

        for (int kt = ks; kt < ke; kt += 64) {
            int kn = min(64, ke - kt);
            // K (and on first iter Q) ready:
            asm volatile("cp.async.wait_group 0;\n");
            __syncthreads();

            // Issue V_kt (overlaps S compute)
#pragma unroll
            for (int t = 0; t < 10; t++) {
                int idx = tid + t * 128;
                int d = idx >> 4, kc = (idx & 15) * 4;
                int bytes = min(max(kn - kc, 0), 4) * 4;
                int scol = (kc < kn) ? (kt + kc) : kt;
                cp16z(sV + (uint32_t)(d * VT_STR + kc) * 4u,
                      g_Vt + (size_t)(h * HD + d) * SEQ + scol, bytes);
            }
            asm volatile("cp.async.commit_group;\n");

            // S = Q K^T
            float sacc[8][4];
#pragma unroll
            for (int nt = 0; nt < 8; nt++)
#pragma unroll
                for (int r = 0; r < 4; r++) sacc[nt][r] = 0.f;

#pragma unroll
            for (int ksp = 0; ksp < 10; ksp++) {
                const int k0 = ksp * 8;
                uint32_t af[4], bf[8][2];
                af[0] = __float_as_uint(Qs[(m0 + g) * QS_STR + k0 + tg]);
                af[1] = __float_as_uint(Qs[(m0 + 8 + g) * QS_STR + k0 + tg]);
                af[2] = __float_as_uint(Qs[(m0 + g) * QS_STR + k0 + tg + 4]);
                af[3] = __float_as_uint(Qs[(m0 + 8 + g) * QS_STR + k0 + tg + 4]);
#pragma unroll
                for (int nt = 0; nt < 8; nt++) {
                    bf[nt][0] = __float_as_uint(Ks[(nt * 8 + g) * QS_STR + k0 + tg]);
                    bf[nt][1] = __float_as_uint(Ks[(nt * 8 + g) * QS_STR + k0 + tg + 4]);
                }
#pragma unroll
                for (int nt = 0; nt < 8; nt++)
                    mma_tf32(sacc[nt], af, bf[nt]);
            }

            __syncthreads();   // all warps done reading Ks

            // Issue K_{kt+64} (overlaps softmax + PV)
            if (kt + 64 < ke) {
                int knn = min(64, ke - (kt + 64));
#pragma unroll
                for (int t = 0; t < 10; t++) {
                    int idx = tid + t * 128;
                    int r = idx / 20, dc = (idx % 20) * 4;
                    int srow = (r < knn) ? (kt + 64 + r) : (kt + 64 - 1);
                    cp16z(sK + (uint32_t)(r * QS_STR + dc) * 4u,
                          g_K + (size_t)srow * DIM + h * HD + dc, (r < knn) ? 16 : 0);
                }
            }
            asm volatile("cp.async.commit_group;\n");

            if (kn < 64) {
#pragma unroll
                for (int nt = 0; nt < 8; nt++) {
                    int c = nt * 8 + 2 * tg;
                    if (c >= kn)     { sacc[nt][0] = -1e30f; sacc[nt][2] = -1e30f; }
                    if (c + 1 >= kn) { sacc[nt][1] = -1e30f; sacc[nt][3] = -1e30f; }
                }
            }

            // Online softmax
#pragma unroll
            for (int half = 0; half < 2; half++) {
                const int b = half * 2;
                float mloc = -1e30f;
#pragma unroll
                for (int nt = 0; nt < 8; nt++)
                    mloc = fmaxf(mloc, fmaxf(sacc[nt][b], sacc[nt][b + 1]));
                mloc = fmaxf(mloc, __shfl_xor_sync(0xffffffffu, mloc, 1));
                mloc = fmaxf(mloc, __shfl_xor_sync(0xffffffffu, mloc, 2));
                float mn = fmaxf(mrow[half], mloc);
                float fac = __expf(mrow[half] - mn);
                mrow[half] = mn;
                float rs = 0.f;
#pragma unroll
                for (int nt = 0; nt < 8; nt++) {
                    float p0 = __expf(sacc[nt][b] - mn);
                    float p1 = __expf(sacc[nt][b + 1] - mn);
                    sacc[nt][b] = p0; sacc[nt][b + 1] = p1;
                    rs += p0 + p1;
                }
                rs += __shfl_xor_sync(0xffffffffu, rs, 1);
                rs += __shfl_xor_sync(0xffffffffu, rs, 2);
                lrow[half] = lrow[half] * fac + rs;
#pragma unroll
                for (int nt = 0; nt < 10; nt++) { o[nt][b] *= fac; o[nt][b + 1] *= fac; }
            }

            // Stage P (tf32) — warp-private rows
#pragma unroll
            for (int nt = 0; nt < 8; nt++) {
                int c = nt * 8 + 2 * tg;
                Ps[(m0 + g) * VT_STR + c]         = f2tf32(sacc[nt][0]);
                Ps[(m0 + g) * VT_STR + c + 1]     = f2tf32(sacc[nt][1]);
                Ps[(m0 + 8 + g) * VT_STR + c]     = f2tf32(sacc[nt][2]);
                Ps[(m0 + 8 + g) * VT_STR + c + 1] = f2tf32(sacc[nt][3]);
            }

            // Wait V (newest group = K_{kt+64} may still be in flight)
            asm volatile("cp.async.wait_group 1;\n");
            __syncthreads();

            // O += P V
#pragma unroll
            for (int ksp = 0; ksp < 8; ksp++) {
                const int k0 = ksp * 8;
                uint32_t af[4], bf[10][2];
                af[0] = __float_as_uint(Ps[(m0 + g) * VT_STR + k0 + tg]);
                af[1] = __float_as_uint(Ps[(m0 + 8 + g) * VT_STR + k0 + tg]);
                af[2] = __float_as_uint(Ps[(m0 + g) * VT_STR + k0 + tg + 4]);
                af[3] = __float_as_uint(Ps[(m0 + 8 + g) * VT_STR + k0 + tg + 4]);
#pragma unroll
                for (int nt = 0; nt < 10; nt++) {
                    bf[nt][0] = __float_as_uint(Vt[(nt * 8 + g) * VT_STR + k0 + tg]);
                    bf[nt][1] = __float_as_uint(Vt[(nt * 8 + g) * VT_STR + k0 + tg + 4]);
                }
#pragma unroll
                for (int nt = 0; nt < 10; nt++)
                    mma_tf32(o[nt], af, bf[nt]);
            }
        }

        const float inv0 = 1.f / lrow[0];
        const float inv1 = 1.f / lrow[1];
#pragma unroll
        for (int nt = 0; nt < 10; nt++) {
            int c = h * HD + nt * 8 + 2 * tg;
            *(float2*)(out + (size_t)(qb + m0 + g) * DIM + c) =
                make_float2(f2tf32(o[nt][0] * inv0), f2tf32(o[nt][1] * inv0));
            *(float2*)(out + (size_t)(qb + m0 + 8 + g) * DIM + c) =
                make_float2(f2tf32(o[nt][2] * inv1), f2tf32(o[nt][3] * inv1));
        }
    }
}

// ---------------------------------------------------------------------------
extern "C" void kernel_launch(void* const* d_in, const int* in_sizes, int n_in,
                              void* d_out, int out_size)
{
    const float* X  = (const float*)d_in[0];
    const float* Wq = (const float*)d_in[1];
    const float* bq = (const float*)d_in[2];
    const float* Wk = (const float*)d_in[3];
    const float* bk = (const float*)d_in[4];
    const float* Wv = (const float*)d_in[5];
    const float* bv = (const float*)d_in[6];
    const float* Wo = (const float*)d_in[7];
    const float* bo = (const float*)d_in[8];
    const float* cs = (const float*)d_in[9];
    const float* sn = (const float*)d_in[10];
    const int*   cu = (const int*)d_in[11];
    float* out = (float*)d_out;

    void *pQ, *pK, *pVt, *pA, *pXr, *pWq, *pWk, *pWv, *pWo;
    cudaGetSymbolAddress(&pQ, g_Q);
    cudaGetSymbolAddress(&pK, g_K);
    cudaGetSymbolAddress(&pVt, g_Vt);
    cudaGetSymbolAddress(&pA, g_A);
    cudaGetSymbolAddress(&pXr, g_Xr);
    cudaGetSymbolAddress(&pWq, g_Wqr);
    cudaGetSymbolAddress(&pWk, g_Wkr);
    cudaGetSymbolAddress(&pWv, g_Wvr);
    cudaGetSymbolAddress(&pWo, g_Wor);

    cudaFuncSetAttribute(gemm_tf32_pipe<false>,
                         cudaFuncAttributeMaxDynamicSharedMemorySize, GEMM_SMEM);
    cudaFuncSetAttribute(gemm_tf32_pipe<true>,
                         cudaFuncAttributeMaxDynamicSharedMemorySize, GEMM_SMEM);
    cudaFuncSetAttribute(attn_mma,
                         cudaFuncAttributeMaxDynamicSharedMemorySize, ATTN_SMEM);

    const int ntot = NX4 + 4 * NW4;
    dim3 gg(DIM / BN, SEQ / BM);       // (8, 16) = 128 CTAs
    dim3 gb(256);

    // L1: fused cvt   L2..L4: QKV GEMMs   L5: rope   L6: attention (ncu window)
    cvt_all<<<(ntot + 255) / 256, 256>>>(X, Wq, Wk, Wv, Wo);

    gemm_tf32_pipe<false><<<gg, gb, GEMM_SMEM>>>((const float*)pXr, (const float*)pWq, bq, (float*)pQ, SEQ, DIM, DIM);
    gemm_tf32_pipe<false><<<gg, gb, GEMM_SMEM>>>((const float*)pXr, (const float*)pWk, bk, (float*)pK, SEQ, DIM, DIM);
    gemm_tf32_pipe<true ><<<gg, gb, GEMM_SMEM>>>((const float*)pXr, (const float*)pWv, bv, (float*)pVt, SEQ, DIM, DIM);

    int rope_total = SEQ * NH * (HD / 2);
    rope_kernel<<<(rope_total + 255) / 256, 256>>>(cs, sn);

    attn_mma<<<ATT_GRID, 128, ATTN_SMEM>>>(cu, (float*)pA);

    gemm_tf32_pipe<false><<<gg, gb, GEMM_SMEM>>>((const float*)pA, (const float*)pWo, bo, out, SEQ, DIM, DIM);
}